// round 15
// baseline (speedup 1.0000x reference)
#include <cuda_runtime.h>

// Problem constants
#define NB   8
#define CCH  20
#define HH_  64
#define WW_  2048
#define HW   (HH_ * WW_)
#define TOT  (NB * CCH * HW)

// Tiling: each block: 10 channels x 4 rows x 128 cols
#define CC   10
#define HT   4
#define WT   128
#define HT2  8            // HT + 4 halo rows
#define WVAL 132          // WT + 4 valid cols
#define WSTR 136          // padded row stride (floats)

// smem: poisoned xyz tile only
#define SMEM_FLOATS (3 * HT2 * WSTR)               // 3264
#define SMEM_BYTES  (SMEM_FLOATS * 4)              // 13056

#define POISON 1e18f
#define FULLMASK 0xffffffffu

__global__ __launch_bounds__(128, 6)
void lcxyz_kernel(const float* __restrict__ xyz,
                  const float* __restrict__ softmax,
                  const unsigned int* __restrict__ mask,  // 4-byte 0/1: word!=0
                  float* __restrict__ out)
{
    extern __shared__ float smem[];
    float* s_xyz = smem;              // [3][HT2][WSTR], poisoned where masked/out-of-frame

    const int tid  = threadIdx.x;
    const int wid  = tid >> 5;
    const int lane = tid & 31;

    const int n    = blockIdx.z >> 1;
    const int c0   = (blockIdx.z & 1) * CC;
    const int h0   = blockIdx.y * HT;
    const int w0   = blockIdx.x * WT;

    // ---- stage xyz with poison masking ----
    #pragma unroll 1
    for (int r = wid; r < HT2; r += 4) {
        const int hh = h0 + r - 2;
        const bool hv = (hh >= 0) && (hh < HH_);
        const unsigned int* msrc = mask + (size_t)(n * HH_ + hh) * WW_;
        const float* x0 = xyz + ((size_t)(n * 3 + 0) * HH_ + hh) * WW_;
        const float* x1 = x0 + (size_t)HW;
        const float* x2 = x1 + (size_t)HW;
        float* d0 = s_xyz + (0 * HT2 + r) * WSTR;
        float* d1 = s_xyz + (1 * HT2 + r) * WSTR;
        float* d2 = s_xyz + (2 * HT2 + r) * WSTR;
        #pragma unroll
        for (int idx = lane; idx < WVAL; idx += 32) {
            const int ww = w0 + idx - 2;
            const bool ok = hv && ((unsigned)ww < (unsigned)WW_);
            if (ok && msrc[ww] != 0u) {
                d0[idx] = x0[ww];
                d1[idx] = x1[ww];
                d2[idx] = x2[ww];
            } else {
                d0[idx] = POISON;
                d1[idx] = POISON;
                d2[idx] = POISON;
            }
        }
    }

    // ---- center xyz from GLOBAL (always real, even if masked) ----
    const int ty = wid;
    const int wl = lane << 2;
    const int gw = w0 + wl;
    const int gh = h0 + ty;

    float xc0[4], xc1[4], xc2[4];
    {
        const size_t cb = ((size_t)(n * 3) * HH_ + gh) * WW_ + gw;
        float4 a = *(const float4*)&xyz[cb];
        float4 b = *(const float4*)&xyz[cb + HW];
        float4 c = *(const float4*)&xyz[cb + 2 * (size_t)HW];
        xc0[0]=a.x; xc0[1]=a.y; xc0[2]=a.z; xc0[3]=a.w;
        xc1[0]=b.x; xc1[1]=b.y; xc1[2]=b.z; xc1[3]=b.w;
        xc2[0]=c.x; xc2[1]=c.y; xc2[2]=c.z; xc2[3]=c.w;
    }

    float acc[CC][4];
    #pragma unroll
    for (int c = 0; c < CC; ++c)
        #pragma unroll
        for (int o = 0; o < 4; ++o) acc[c][o] = 0.0f;

    __syncthreads();

    #pragma unroll 1
    for (int di = 0; di < 5; ++di) {
        const int r = ty + di;

        // xyz window: phys cols wl..wl+7, 3 channels (6 x LDS.128)
        float xv0[8], xv1[8], xv2[8];
        {
            const float4* p = (const float4*)&s_xyz[(0 * HT2 + r) * WSTR + wl];
            float4 a = p[0], b = p[1];
            xv0[0]=a.x; xv0[1]=a.y; xv0[2]=a.z; xv0[3]=a.w;
            xv0[4]=b.x; xv0[5]=b.y; xv0[6]=b.z; xv0[7]=b.w;
        }
        {
            const float4* p = (const float4*)&s_xyz[(1 * HT2 + r) * WSTR + wl];
            float4 a = p[0], b = p[1];
            xv1[0]=a.x; xv1[1]=a.y; xv1[2]=a.z; xv1[3]=a.w;
            xv1[4]=b.x; xv1[5]=b.y; xv1[6]=b.z; xv1[7]=b.w;
        }
        {
            const float4* p = (const float4*)&s_xyz[(2 * HT2 + r) * WSTR + wl];
            float4 a = p[0], b = p[1];
            xv2[0]=a.x; xv2[1]=a.y; xv2[2]=a.z; xv2[3]=a.w;
            xv2[4]=b.x; xv2[5]=b.y; xv2[6]=b.z; xv2[7]=b.w;
        }

        // 20 weights: exp(-d2/2); poisoned sources give exactly 0
        float wgt[4][5];
        #pragma unroll
        for (int dj = 0; dj < 5; ++dj) {
            #pragma unroll
            for (int o = 0; o < 4; ++o) {
                float dx = xv0[o + dj] - xc0[o];
                float dy = xv1[o + dj] - xc1[o];
                float dz = xv2[o + dj] - xc2[o];
                float d2 = dx * dx + dy * dy + dz * dz;
                wgt[o][dj] = __expf(-0.5f * d2);
            }
        }

        // source row clamped into frame (out-of-frame taps have wgt==0)
        const int rg  = gh + di - 2;
        const int hcl = min(max(rg, 0), HH_ - 1);
        const int base0 = ((n * CCH + c0) * HH_ + hcl) * WW_ + gw;  // own float4 index

        // 10 channels: 1 aligned LDG.128 + 4 SHFL halo + 2 edge-lane fixups
        #pragma unroll
        for (int c = 0; c < CC; ++c) {
            const int base = base0 + c * HW;
            float4 b = *(const float4*)&softmax[base];   // cols gw..gw+3

            // halo from neighbor lanes
            float lz = __shfl_up_sync(FULLMASK, b.z, 1);   // col gw-2
            float lw = __shfl_up_sync(FULLMASK, b.w, 1);   // col gw-1
            float rx = __shfl_down_sync(FULLMASK, b.x, 1); // col gw+4
            float ry = __shfl_down_sync(FULLMASK, b.y, 1); // col gw+5

            // warp-edge fixups (1 wavefront each; clamped slots are weight-zero)
            if (lane == 0) {
                int i0 = base - 2;
                if (c == 0) i0 = max(i0, 0);
                float2 t = *(const float2*)&softmax[i0];
                lz = t.x; lw = t.y;
            }
            if (lane == 31) {
                int i2 = base + 4;
                if (c == CC - 1) i2 = min(i2, TOT - 2);
                float2 t = *(const float2*)&softmax[i2];
                rx = t.x; ry = t.y;
            }

            float s[8];
            s[0]=lz;  s[1]=lw;  s[2]=b.x; s[3]=b.y;
            s[4]=b.z; s[5]=b.w; s[6]=rx;  s[7]=ry;

            #pragma unroll
            for (int o = 0; o < 4; ++o) {
                #pragma unroll
                for (int dj = 0; dj < 5; ++dj)
                    acc[c][o] += wgt[o][dj] * s[o + dj];
            }
        }
    }

    // ---- store: float4 per channel ----
    #pragma unroll
    for (int c = 0; c < CC; ++c) {
        float4 v = make_float4(acc[c][0], acc[c][1], acc[c][2], acc[c][3]);
        *(float4*)&out[((size_t)(n * CCH + c0 + c) * HH_ + gh) * WW_ + gw] = v;
    }
}

extern "C" void kernel_launch(void* const* d_in, const int* in_sizes, int n_in,
                              void* d_out, int out_size)
{
    const float*        xyz  = (const float*)d_in[0];
    const float*        sm   = (const float*)d_in[1];
    const unsigned int* mask = (const unsigned int*)d_in[2];
    float*              out  = (float*)d_out;

    (void)in_sizes; (void)n_in; (void)out_size;

    dim3 grid(WW_ / WT, HH_ / HT, NB * 2);   // 16 x 16 x 16 = 4096 blocks
    lcxyz_kernel<<<grid, 128, SMEM_BYTES>>>(xyz, sm, mask, out);
}

// round 16
// speedup vs baseline: 1.4309x; 1.4309x over previous
#include <cuda_runtime.h>

// Problem constants
#define NB   8
#define CCH  20
#define HH_  64
#define WW_  2048
#define HW   (HH_ * WW_)
#define TOT  (NB * CCH * HW)

// Tiling: each block: 10 channels x 4 rows x 128 cols
#define CC   10
#define HT   4
#define WT   128
#define HT2  8            // HT + 4 halo rows
#define WVAL 132          // WT + 4 valid cols
#define WSTR 136          // padded row stride (floats)

// smem: poisoned xyz tile + edge table
#define XYZ_FLOATS (3 * HT2 * WSTR)                // 3264
#define OFF_EDGE   XYZ_FLOATS                      // float4 s_edge[CC*HT2]
#define SMEM_FLOATS (XYZ_FLOATS + CC * HT2 * 4)    // 3264 + 320
#define SMEM_BYTES  (SMEM_FLOATS * 4)              // 14336

#define POISON 1e18f
#define FULLMASK 0xffffffffu

__global__ __launch_bounds__(128, 6)
void lcxyz_kernel(const float* __restrict__ xyz,
                  const float* __restrict__ softmax,
                  const unsigned int* __restrict__ mask,  // 4-byte 0/1: word!=0
                  float* __restrict__ out)
{
    extern __shared__ float smem[];
    float*  s_xyz  = smem;                          // [3][HT2][WSTR]
    float4* s_edge = (float4*)(smem + OFF_EDGE);    // [CC][HT2]: {l0,l1,r0,r1}

    const int tid  = threadIdx.x;
    const int wid  = tid >> 5;
    const int lane = tid & 31;

    const int n    = blockIdx.z >> 1;
    const int c0   = (blockIdx.z & 1) * CC;
    const int h0   = blockIdx.y * HT;
    const int w0   = blockIdx.x * WT;

    // ---- stage xyz with poison masking ----
    #pragma unroll 1
    for (int r = wid; r < HT2; r += 4) {
        const int hh = h0 + r - 2;
        const bool hv = (hh >= 0) && (hh < HH_);
        const unsigned int* msrc = mask + (size_t)(n * HH_ + hh) * WW_;
        const float* x0 = xyz + ((size_t)(n * 3 + 0) * HH_ + hh) * WW_;
        const float* x1 = x0 + (size_t)HW;
        const float* x2 = x1 + (size_t)HW;
        float* d0 = s_xyz + (0 * HT2 + r) * WSTR;
        float* d1 = s_xyz + (1 * HT2 + r) * WSTR;
        float* d2 = s_xyz + (2 * HT2 + r) * WSTR;
        #pragma unroll
        for (int idx = lane; idx < WVAL; idx += 32) {
            const int ww = w0 + idx - 2;
            const bool ok = hv && ((unsigned)ww < (unsigned)WW_);
            if (ok && msrc[ww] != 0u) {
                d0[idx] = x0[ww];
                d1[idx] = x1[ww];
                d2[idx] = x2[ww];
            } else {
                d0[idx] = POISON;
                d1[idx] = POISON;
                d2[idx] = POISON;
            }
        }
    }

    // ---- stage softmax warp-edge table: (c, r) -> {w0-2, w0-1, w0+WT, w0+WT+1} ----
    // Clamped slots always correspond to out-of-frame taps (poisoned xyz -> weight 0),
    // so clamping just keeps the value finite and the index in-buffer.
    if (tid < CC * HT2) {
        const int c  = tid >> 3;        // 0..9
        const int r  = tid & 7;         // 0..7
        const int hcl = min(max(h0 + r - 2, 0), HH_ - 1);
        const float* row = softmax + ((size_t)(n * CCH + c0 + c) * HH_ + hcl) * WW_;
        const int l0 = max(w0 - 2, 0);
        const int l1 = max(w0 - 1, 0);
        const int r0 = min(w0 + WT,     WW_ - 1);
        const int r1 = min(w0 + WT + 1, WW_ - 1);
        s_edge[tid] = make_float4(row[l0], row[l1], row[r0], row[r1]);
    }

    // ---- center xyz from GLOBAL (always real, even if masked) ----
    const int ty = wid;
    const int wl = lane << 2;
    const int gw = w0 + wl;
    const int gh = h0 + ty;

    float xc0[4], xc1[4], xc2[4];
    {
        const size_t cb = ((size_t)(n * 3) * HH_ + gh) * WW_ + gw;
        float4 a = *(const float4*)&xyz[cb];
        float4 b = *(const float4*)&xyz[cb + HW];
        float4 c = *(const float4*)&xyz[cb + 2 * (size_t)HW];
        xc0[0]=a.x; xc0[1]=a.y; xc0[2]=a.z; xc0[3]=a.w;
        xc1[0]=b.x; xc1[1]=b.y; xc1[2]=b.z; xc1[3]=b.w;
        xc2[0]=c.x; xc2[1]=c.y; xc2[2]=c.z; xc2[3]=c.w;
    }

    float acc[CC][4];
    #pragma unroll
    for (int c = 0; c < CC; ++c)
        #pragma unroll
        for (int o = 0; o < 4; ++o) acc[c][o] = 0.0f;

    const bool is_l = (lane == 0);
    const bool is_r = (lane == 31);

    __syncthreads();

    #pragma unroll 1
    for (int di = 0; di < 5; ++di) {
        const int r = ty + di;

        // xyz window: phys cols wl..wl+7, 3 channels (6 x LDS.128)
        float xv0[8], xv1[8], xv2[8];
        {
            const float4* p = (const float4*)&s_xyz[(0 * HT2 + r) * WSTR + wl];
            float4 a = p[0], b = p[1];
            xv0[0]=a.x; xv0[1]=a.y; xv0[2]=a.z; xv0[3]=a.w;
            xv0[4]=b.x; xv0[5]=b.y; xv0[6]=b.z; xv0[7]=b.w;
        }
        {
            const float4* p = (const float4*)&s_xyz[(1 * HT2 + r) * WSTR + wl];
            float4 a = p[0], b = p[1];
            xv1[0]=a.x; xv1[1]=a.y; xv1[2]=a.z; xv1[3]=a.w;
            xv1[4]=b.x; xv1[5]=b.y; xv1[6]=b.z; xv1[7]=b.w;
        }
        {
            const float4* p = (const float4*)&s_xyz[(2 * HT2 + r) * WSTR + wl];
            float4 a = p[0], b = p[1];
            xv2[0]=a.x; xv2[1]=a.y; xv2[2]=a.z; xv2[3]=a.w;
            xv2[4]=b.x; xv2[5]=b.y; xv2[6]=b.z; xv2[7]=b.w;
        }

        // 20 weights: exp(-d2/2); poisoned sources give exactly 0
        float wgt[4][5];
        #pragma unroll
        for (int dj = 0; dj < 5; ++dj) {
            #pragma unroll
            for (int o = 0; o < 4; ++o) {
                float dx = xv0[o + dj] - xc0[o];
                float dy = xv1[o + dj] - xc1[o];
                float dz = xv2[o + dj] - xc2[o];
                float d2 = dx * dx + dy * dy + dz * dz;
                wgt[o][dj] = __expf(-0.5f * d2);
            }
        }

        // source row clamped into frame (out-of-frame taps have wgt==0)
        const int rg  = gh + di - 2;
        const int hcl = min(max(rg, 0), HH_ - 1);
        const int base0 = ((n * CCH + c0) * HH_ + hcl) * WW_ + gw;  // own float4

        // 10 channels: 1 LDG.128 + 4 SHFL + 1 broadcast LDS.128 + 4 SEL (branchless)
        #pragma unroll
        for (int c = 0; c < CC; ++c) {
            float4 b = *(const float4*)&softmax[base0 + c * HW];   // cols gw..gw+3

            float lz = __shfl_up_sync(FULLMASK, b.z, 1);   // col gw-2
            float lw = __shfl_up_sync(FULLMASK, b.w, 1);   // col gw-1
            float rx = __shfl_down_sync(FULLMASK, b.x, 1); // col gw+4
            float ry = __shfl_down_sync(FULLMASK, b.y, 1); // col gw+5

            float4 e = s_edge[c * HT2 + r];                // warp-edge quad (broadcast)
            lz = is_l ? e.x : lz;
            lw = is_l ? e.y : lw;
            rx = is_r ? e.z : rx;
            ry = is_r ? e.w : ry;

            float s[8];
            s[0]=lz;  s[1]=lw;  s[2]=b.x; s[3]=b.y;
            s[4]=b.z; s[5]=b.w; s[6]=rx;  s[7]=ry;

            #pragma unroll
            for (int o = 0; o < 4; ++o) {
                #pragma unroll
                for (int dj = 0; dj < 5; ++dj)
                    acc[c][o] += wgt[o][dj] * s[o + dj];
            }
        }
    }

    // ---- store: float4 per channel ----
    #pragma unroll
    for (int c = 0; c < CC; ++c) {
        float4 v = make_float4(acc[c][0], acc[c][1], acc[c][2], acc[c][3]);
        *(float4*)&out[((size_t)(n * CCH + c0 + c) * HH_ + gh) * WW_ + gw] = v;
    }
}

extern "C" void kernel_launch(void* const* d_in, const int* in_sizes, int n_in,
                              void* d_out, int out_size)
{
    const float*        xyz  = (const float*)d_in[0];
    const float*        sm   = (const float*)d_in[1];
    const unsigned int* mask = (const unsigned int*)d_in[2];
    float*              out  = (float*)d_out;

    (void)in_sizes; (void)n_in; (void)out_size;

    dim3 grid(WW_ / WT, HH_ / HT, NB * 2);   // 16 x 16 x 16 = 4096 blocks
    lcxyz_kernel<<<grid, 128, SMEM_BYTES>>>(xyz, sm, mask, out);
}